// round 7
// baseline (speedup 1.0000x reference)
#include <cuda_runtime.h>

#define BB 256
#define SS 512
#define TT 128

// Scratch (no allocations allowed in kernel_launch)
__device__ __align__(16) float g_ET[TT * TT];  // g_ET[t*TT+i] = exp(trans[i][t])
__device__ float g_gold[BB];
__device__ float g_logZ[BB];
__device__ int   g_tagStride;      // 1 = int32 tags, 2 = int64 tags

// ---------------------------------------------------------------------------
// Kernel 0: detect tag dtype (odd 32-bit words all zero => int64 buffer)
// ---------------------------------------------------------------------------
__global__ void detect_tags_kernel(const unsigned int* __restrict__ tags32) {
    unsigned int acc = 0;
    for (int i = threadIdx.x; i < 256; i += 32)
        acc |= tags32[2 * i + 1];
    #pragma unroll
    for (int o = 16; o > 0; o >>= 1)
        acc |= __shfl_xor_sync(0xffffffffu, acc, o);
    if (threadIdx.x == 0) g_tagStride = (acc == 0u) ? 2 : 1;
}

// ---------------------------------------------------------------------------
// Kernel 1: g_ET[t][i] = exp(trans[i][t])   (transposed: column t contiguous)
// ---------------------------------------------------------------------------
__global__ void expT_kernel(const float* __restrict__ trans) {
    int i = blockIdx.x * blockDim.x + threadIdx.x;
    if (i < TT * TT) {
        int r = i >> 7;
        int c = i & (TT - 1);
        g_ET[c * TT + r] = __expf(trans[i]);
    }
}

// ---------------------------------------------------------------------------
// Kernel 2: gold score per batch
// ---------------------------------------------------------------------------
__global__ void gold_kernel(const float* __restrict__ emis,
                            const int* __restrict__ tags,
                            const float* __restrict__ trans) {
    int b = blockIdx.x;
    int tid = threadIdx.x;
    int lane = tid & 31;
    int wid = tid >> 5;

    const int stride = g_tagStride;
    const int* tg = tags + b * SS * stride;
    const float* eb = emis + (size_t)b * SS * TT;

    float sum = 0.f;
    for (int s = tid; s < SS; s += blockDim.x) {
        int cur = tg[s * stride];
        sum += eb[s * TT + cur];
        if (s < SS - 1) {
            int nxt = tg[(s + 1) * stride];
            sum += trans[cur * TT + nxt];
        }
    }
    #pragma unroll
    for (int o = 16; o > 0; o >>= 1)
        sum += __shfl_xor_sync(0xffffffffu, sum, o);
    __shared__ float red[4];
    if (lane == 0) red[wid] = sum;
    __syncthreads();
    if (tid == 0) g_gold[b] = red[0] + red[1] + red[2] + red[3];
}

// ---------------------------------------------------------------------------
// Kernel 3: forward algorithm. 256 threads/CTA, 1 batch/CTA.
// Thread k: quarter h = k&3 (rows [32h,32h+32)), states t0 = 2*(k>>2), t0+1.
// Each LDS.128 of the P quarter feeds FMAs of BOTH columns (halved L1 work).
// Scaled state P_s[t] = exp(alpha_s[t] - M_s), anchor M_s = alpha_{s-1}[0]
// published one step early by thread 0:
//   acc_s[t]   = sum_i P_{s-1}[i] * E[i][t]
//   alpha_s[t] = log(acc_s[t]) + M_{s-1} + e_s[t]
//   P_s[t]     = acc_s[t] * exp(e_s[t] + M_{s-1} - M_s)    (exp off the path)
// Quarter-partials combined with shfl_xor(1) + shfl_xor(2) (same warp).
// One barrier per step; sp double-buffered; quarters at 36-float stride so
// the 4 broadcast groups hit banks {0-3},{4-7},{8-11},{12-15}.
// Epilogue (exp, LDG of emissions, STS of P) done only by h==0 threads;
// emissions fetched as one float2 per state pair.
// ---------------------------------------------------------------------------
__global__ void __launch_bounds__(256, 2) forward_kernel(const float* __restrict__ emis) {
    int b = blockIdx.x;
    int k = threadIdx.x;
    int q = k >> 2;           // state pair index 0..63
    int h = k & 3;            // quarter 0..3
    int lane = k & 31;
    int wid = k >> 5;

    __shared__ __align__(16) float sp[2][144];   // quarters at 0,36,72,108
    __shared__ float moff[2];
    __shared__ float smax[8];
    __shared__ float ssum[8];

    const int t0 = 2 * q;

    // E chunks: columns t0 and t0+1, rows [32h, 32h+32), packed f32x2
    unsigned long long Ea[16], Eb[16];
    {
        const ulonglong2* ca = (const ulonglong2*)(g_ET + t0 * TT + 32 * h);
        const ulonglong2* cb = (const ulonglong2*)(g_ET + (t0 + 1) * TT + 32 * h);
        #pragma unroll
        for (int j = 0; j < 8; j++) {
            ulonglong2 va = ca[j]; Ea[2 * j] = va.x; Ea[2 * j + 1] = va.y;
            ulonglong2 vb = cb[j]; Eb[2 * j] = vb.x; Eb[2 * j + 1] = vb.y;
        }
    }

    const float* ebq = emis + (size_t)b * SS * TT + t0;   // emissions for pair
    const int pos0 = 36 * (t0 >> 5) + (t0 & 31);          // padded P position

    // --- init: P_0 into sp[1]; M_0 = M_1 = e_0[0] into moff[1]
    float e_cur0 = 0.f, e_cur1 = 0.f;
    if (h == 0) {
        float2 e0 = *(const float2*)ebq;
        if (k == 0) moff[1] = e0.x;
        e_cur0 = e0.x; e_cur1 = e0.y;
    }
    __syncthreads();
    float m_prev = moff[1];
    if (h == 0) {
        float2 p0 = make_float2(__expf(e_cur0 - m_prev), __expf(e_cur1 - m_prev));
        *(float2*)&sp[1][pos0] = p0;
        float2 e1 = *(const float2*)(ebq + TT);
        e_cur0 = e1.x; e_cur1 = e1.y;
    }

    float z0 = 0.f, z1 = 0.f;   // final alphas (h==0)

    for (int s = 1; s < SS; s++) {
        // prefetch next emissions (h==0 only)
        float2 en = make_float2(0.f, 0.f);
        if (h == 0 && s + 1 < SS) en = *(const float2*)(ebq + (s + 1) * TT);

        __syncthreads();                         // the ONLY barrier per step
        float m_new = moff[s & 1];               // M_s = alpha_{s-1}[0]

        // quarter-dot for both columns: reuse each loaded P float4 twice
        const ulonglong2* pbuf = (const ulonglong2*)(sp[s & 1] + 36 * h);
        unsigned long long a0 = 0ull, a1 = 0ull, b0 = 0ull, b1 = 0ull;
        #pragma unroll
        for (int j = 0; j < 8; j++) {
            ulonglong2 pv = pbuf[j];
            asm("fma.rn.f32x2 %0, %1, %2, %0;" : "+l"(a0) : "l"(pv.x), "l"(Ea[2 * j]));
            asm("fma.rn.f32x2 %0, %1, %2, %0;" : "+l"(a1) : "l"(pv.y), "l"(Ea[2 * j + 1]));
            asm("fma.rn.f32x2 %0, %1, %2, %0;" : "+l"(b0) : "l"(pv.x), "l"(Eb[2 * j]));
            asm("fma.rn.f32x2 %0, %1, %2, %0;" : "+l"(b1) : "l"(pv.y), "l"(Eb[2 * j + 1]));
        }
        float al, ah, bl, bh, cl, ch, dl, dh;
        asm("mov.b64 {%0,%1}, %2;" : "=f"(al), "=f"(ah) : "l"(a0));
        asm("mov.b64 {%0,%1}, %2;" : "=f"(bl), "=f"(bh) : "l"(a1));
        asm("mov.b64 {%0,%1}, %2;" : "=f"(cl), "=f"(ch) : "l"(b0));
        asm("mov.b64 {%0,%1}, %2;" : "=f"(dl), "=f"(dh) : "l"(b1));
        float accA = (al + ah) + (bl + bh);
        float accB = (cl + ch) + (dl + dh);

        // combine the 4 quarters (threads k^1, k^2 are in the same warp)
        accA += __shfl_xor_sync(0xffffffffu, accA, 1);
        accB += __shfl_xor_sync(0xffffffffu, accB, 1);
        accA += __shfl_xor_sync(0xffffffffu, accA, 2);
        accB += __shfl_xor_sync(0xffffffffu, accB, 2);

        if (s == SS - 1) {
            if (h == 0) {   // m_prev is still M_{SS-2}; e_cur = e_{SS-1}
                z0 = __logf(accA) + m_prev + e_cur0;
                z1 = __logf(accB) + m_prev + e_cur1;
            }
            break;
        }

        if (h == 0) {
            float w0 = __expf(e_cur0 + (m_prev - m_new));
            float w1 = __expf(e_cur1 + (m_prev - m_new));
            *(float2*)&sp[(s + 1) & 1][pos0] = make_float2(accA * w0, accB * w1);
            if (k == 0)
                moff[(s + 1) & 1] = __logf(accA) + m_prev + e_cur0;  // M_{s+1}
            e_cur0 = en.x;
            e_cur1 = en.y;
        }
        m_prev = m_new;
    }

    // ---- logZ = logsumexp over the 128 final alphas (h==0 holds 2 each) ----
    float mx = (h == 0) ? fmaxf(z0, z1) : -1e30f;
    #pragma unroll
    for (int o = 16; o > 0; o >>= 1)
        mx = fmaxf(mx, __shfl_xor_sync(0xffffffffu, mx, o));
    if (lane == 0) smax[wid] = mx;
    __syncthreads();
    mx = smax[0];
    #pragma unroll
    for (int wv = 1; wv < 8; wv++) mx = fmaxf(mx, smax[wv]);

    float v = (h == 0) ? (__expf(z0 - mx) + __expf(z1 - mx)) : 0.f;
    #pragma unroll
    for (int o = 16; o > 0; o >>= 1)
        v += __shfl_xor_sync(0xffffffffu, v, o);
    if (lane == 0) ssum[wid] = v;
    __syncthreads();
    if (k == 0) {
        float total = 0.f;
        #pragma unroll
        for (int wv = 0; wv < 8; wv++) total += ssum[wv];
        g_logZ[b] = __logf(total) + mx;
    }
}

// ---------------------------------------------------------------------------
// Kernel 4: final scalar: mean_b(-gold[b] + logZ[b])
// ---------------------------------------------------------------------------
__global__ void finalize_kernel(float* __restrict__ out) {
    int t = threadIdx.x;   // 256 threads
    int lane = t & 31;
    int wid = t >> 5;

    float v = -g_gold[t] + g_logZ[t];
    #pragma unroll
    for (int o = 16; o > 0; o >>= 1)
        v += __shfl_xor_sync(0xffffffffu, v, o);
    __shared__ float red[8];
    if (lane == 0) red[wid] = v;
    __syncthreads();
    if (t == 0) {
        float total = 0.f;
        #pragma unroll
        for (int w = 0; w < 8; w++) total += red[w];
        out[0] = total / (float)BB;
    }
}

// ---------------------------------------------------------------------------
extern "C" void kernel_launch(void* const* d_in, const int* in_sizes, int n_in,
                              void* d_out, int out_size) {
    const float* emis  = (const float*)d_in[0];   // (256, 512, 128) f32
    const int*   tags  = (const int*)d_in[1];     // (256, 512) i32/i64 (detected)
    const float* trans = (const float*)d_in[2];   // (128, 128) f32
    float* out = (float*)d_out;

    detect_tags_kernel<<<1, 32>>>((const unsigned int*)tags);
    expT_kernel<<<(TT * TT + 127) / 128, 128>>>(trans);
    gold_kernel<<<BB, 128>>>(emis, tags, trans);
    forward_kernel<<<BB, 256>>>(emis);
    finalize_kernel<<<1, BB>>>(out);
}

// round 9
// speedup vs baseline: 1.1983x; 1.1983x over previous
#include <cuda_runtime.h>

#define BB 256
#define SS 512
#define TT 128
#define C0 5.5f   // warmup anchor slope guess (self-corrected after 8 steps)

// Scratch (no allocations allowed in kernel_launch)
__device__ __align__(16) float g_ET[TT * TT];  // g_ET[t*TT+i] = exp(trans[i][t])
__device__ float g_gold[BB];
__device__ float g_logZ[BB];
__device__ int   g_tagStride;      // 1 = int32 tags, 2 = int64 tags

// ---------------------------------------------------------------------------
// Kernel 0: detect tag dtype (odd 32-bit words all zero => int64 buffer)
// ---------------------------------------------------------------------------
__global__ void detect_tags_kernel(const unsigned int* __restrict__ tags32) {
    unsigned int acc = 0;
    for (int i = threadIdx.x; i < 256; i += 32)
        acc |= tags32[2 * i + 1];
    #pragma unroll
    for (int o = 16; o > 0; o >>= 1)
        acc |= __shfl_xor_sync(0xffffffffu, acc, o);
    if (threadIdx.x == 0) g_tagStride = (acc == 0u) ? 2 : 1;
}

// ---------------------------------------------------------------------------
// Kernel 1: g_ET[t][i] = exp(trans[i][t])   (transposed: column t contiguous)
// ---------------------------------------------------------------------------
__global__ void expT_kernel(const float* __restrict__ trans) {
    int i = blockIdx.x * blockDim.x + threadIdx.x;
    if (i < TT * TT) {
        int r = i >> 7;
        int c = i & (TT - 1);
        g_ET[c * TT + r] = __expf(trans[i]);
    }
}

// ---------------------------------------------------------------------------
// Kernel 2: gold score per batch
// ---------------------------------------------------------------------------
__global__ void gold_kernel(const float* __restrict__ emis,
                            const int* __restrict__ tags,
                            const float* __restrict__ trans) {
    int b = blockIdx.x;
    int tid = threadIdx.x;
    int lane = tid & 31;
    int wid = tid >> 5;

    const int stride = g_tagStride;
    const int* tg = tags + b * SS * stride;
    const float* eb = emis + (size_t)b * SS * TT;

    float sum = 0.f;
    for (int s = tid; s < SS; s += blockDim.x) {
        int cur = tg[s * stride];
        sum += eb[s * TT + cur];
        if (s < SS - 1) {
            int nxt = tg[(s + 1) * stride];
            sum += trans[cur * TT + nxt];
        }
    }
    #pragma unroll
    for (int o = 16; o > 0; o >>= 1)
        sum += __shfl_xor_sync(0xffffffffu, sum, o);
    __shared__ float red[4];
    if (lane == 0) red[wid] = sum;
    __syncthreads();
    if (tid == 0) g_gold[b] = red[0] + red[1] + red[2] + red[3];
}

// ---------------------------------------------------------------------------
// Kernel 3: forward algorithm. 128 threads/CTA, 1 batch/CTA, thread t owns
// state t with its full E column in registers (64 packed f32x2).
//
// Scaled state: P_s[t] = exp(alpha_s[t] - M_s). Step s consumes P_{s-1}:
//   acc_s[t]   = sum_{i=0..127} P_{s-1}[i] * E[i][t]     <- FULL column
//   alpha_s[t] = log(acc_s[t]) + M_{s-1} + e_s[t]
//   P_s[t]     = acc_s[t] * exp(e_s[t] + M_{s-1} - M_s)
//
// ANCHORS OFF THE CRITICAL PATH: M_s is published 8 steps in advance by
// thread 0 as a prediction M_{s+8} = alpha_s[0] + 7*dbar (dbar = measured
// mean increment, lag-8 self-correcting). The algebra is EXACT for any
// block-consistent anchors; accuracy only keeps exp() in fp32 range
// (prediction error bound ~ +/-5 in log space, e^5 ~ 150 -- safe).
// Thread 0's __logf is consumed >= 7 steps later, fully hidden.
// Per-step critical path: BAR -> LDS P -> FFMA2 chain -> adds -> FMUL -> STS.
// Emissions prefetched 3 steps ahead. One barrier per step; sp double-buffered.
// ---------------------------------------------------------------------------
__global__ void __launch_bounds__(TT, 2) forward_kernel(const float* __restrict__ emis) {
    int b = blockIdx.x;
    int t = threadIdx.x;
    int lane = t & 31;
    int wid = t >> 5;

    __shared__ __align__(16) float sp[2][TT];
    __shared__ float moff[16];     // anchor ring: M_s at slot s & 15
    __shared__ float ahist[8];     // thread-0 alpha[0] history ring
    __shared__ float smax[4];
    __shared__ float ssum[4];

    // E column t as 64 packed f32x2 (covers ALL 128 rows)
    unsigned long long Ep[TT / 2];
    {
        const ulonglong2* ec = (const ulonglong2*)(g_ET + t * TT);
        #pragma unroll
        for (int j = 0; j < TT / 4; j++) {
            ulonglong2 v = ec[j];
            Ep[2 * j]     = v.x;
            Ep[2 * j + 1] = v.y;
        }
    }

    const float* eb = emis + (size_t)b * SS * TT;

    float e0 = eb[t];
    float abase = __shfl_sync(0xffffffffu, e0, 0);   // e_0[0] (used by t==0)
    // init anchors M_0..M_8 with constant slope; exact M_0 = alpha_0[0]
    if (t == 0) {
        ahist[0] = e0;                     // alpha_0[0]
        #pragma unroll
        for (int s = 0; s <= 8; s++) moff[s] = e0 + (float)s * C0;
    }
    __syncthreads();
    float m_prev = moff[0];                // M_0 = e_0[0]
    sp[1][t] = __expf(e0 - m_prev);        // P_0 (read at s=1 from sp[1])

    // emission pipeline, 3 deep
    float e_c  = eb[1 * TT + t];
    float e_n1 = eb[2 * TT + t];
    float e_n2 = eb[3 * TT + t];

    float z = 0.f;

    for (int s = 1; s < SS; s++) {
        float e_n3 = (s + 3 < SS) ? eb[(s + 3) * TT + t] : 0.f;

        __syncthreads();                    // the ONLY barrier per step
        float m_cur = moff[s & 15];         // published >= 7 steps ago
        float w = __expf(e_c + (m_prev - m_cur));   // independent of the dot

        // acc = sum over ALL 128: 32 LDS.128 (broadcast), 64 FFMA2
        const ulonglong2* pb = (const ulonglong2*)sp[s & 1];
        unsigned long long a0 = 0ull, a1 = 0ull, a2 = 0ull, a3 = 0ull;
        #pragma unroll
        for (int j = 0; j < TT / 4; j += 2) {   // j = 0..31, 32 ulonglong2
            ulonglong2 pv = pb[j];
            ulonglong2 pw = pb[j + 1];
            asm("fma.rn.f32x2 %0, %1, %2, %0;" : "+l"(a0) : "l"(pv.x), "l"(Ep[2 * j]));
            asm("fma.rn.f32x2 %0, %1, %2, %0;" : "+l"(a1) : "l"(pv.y), "l"(Ep[2 * j + 1]));
            asm("fma.rn.f32x2 %0, %1, %2, %0;" : "+l"(a2) : "l"(pw.x), "l"(Ep[2 * j + 2]));
            asm("fma.rn.f32x2 %0, %1, %2, %0;" : "+l"(a3) : "l"(pw.y), "l"(Ep[2 * j + 3]));
        }
        float l0, h0, l1, h1, l2, h2, l3, h3;
        asm("mov.b64 {%0,%1}, %2;" : "=f"(l0), "=f"(h0) : "l"(a0));
        asm("mov.b64 {%0,%1}, %2;" : "=f"(l1), "=f"(h1) : "l"(a1));
        asm("mov.b64 {%0,%1}, %2;" : "=f"(l2), "=f"(h2) : "l"(a2));
        asm("mov.b64 {%0,%1}, %2;" : "=f"(l3), "=f"(h3) : "l"(a3));
        float acc = ((l0 + h0) + (l1 + h1)) + ((l2 + h2) + (l3 + h3));

        if (s == SS - 1) {
            z = __logf(acc) + m_prev + e_c;   // alpha_{SS-1}[t]
            break;
        }

        sp[(s + 1) & 1][t] = acc * w;          // P_s[t]

        if (t == 0) {
            // Publish M_{s+8}; consumed >= 7 steps later (hidden latency).
            float alpha0 = __logf(acc) + m_prev + e_c;     // alpha_s[0] exact
            float aold = ahist[s & 7];                     // alpha_{s-8}[0]
            float dbar = (s >= 8) ? (alpha0 - aold) * 0.125f
                                  : __fdividef(alpha0 - abase, (float)s);
            moff[(s + 8) & 15] = alpha0 + 7.f * dbar;
            ahist[s & 7] = alpha0;
        }

        m_prev = m_cur;
        e_c = e_n1; e_n1 = e_n2; e_n2 = e_n3;
    }

    // ---- logZ = logsumexp_t z[t] (exact max; all 128 threads hold z) ----
    float mx = z;
    #pragma unroll
    for (int o = 16; o > 0; o >>= 1)
        mx = fmaxf(mx, __shfl_xor_sync(0xffffffffu, mx, o));
    if (lane == 0) smax[wid] = mx;
    __syncthreads();
    mx = fmaxf(fmaxf(smax[0], smax[1]), fmaxf(smax[2], smax[3]));

    float v = __expf(z - mx);
    #pragma unroll
    for (int o = 16; o > 0; o >>= 1)
        v += __shfl_xor_sync(0xffffffffu, v, o);
    if (lane == 0) ssum[wid] = v;
    __syncthreads();
    if (t == 0)
        g_logZ[b] = __logf(ssum[0] + ssum[1] + ssum[2] + ssum[3]) + mx;
}

// ---------------------------------------------------------------------------
// Kernel 4: final scalar: mean_b(-gold[b] + logZ[b])
// ---------------------------------------------------------------------------
__global__ void finalize_kernel(float* __restrict__ out) {
    int t = threadIdx.x;   // 256 threads
    int lane = t & 31;
    int wid = t >> 5;

    float v = -g_gold[t] + g_logZ[t];
    #pragma unroll
    for (int o = 16; o > 0; o >>= 1)
        v += __shfl_xor_sync(0xffffffffu, v, o);
    __shared__ float red[8];
    if (lane == 0) red[wid] = v;
    __syncthreads();
    if (t == 0) {
        float total = 0.f;
        #pragma unroll
        for (int w = 0; w < 8; w++) total += red[w];
        out[0] = total / (float)BB;
    }
}

// ---------------------------------------------------------------------------
extern "C" void kernel_launch(void* const* d_in, const int* in_sizes, int n_in,
                              void* d_out, int out_size) {
    const float* emis  = (const float*)d_in[0];   // (256, 512, 128) f32
    const int*   tags  = (const int*)d_in[1];     // (256, 512) i32/i64 (detected)
    const float* trans = (const float*)d_in[2];   // (128, 128) f32
    float* out = (float*)d_out;

    detect_tags_kernel<<<1, 32>>>((const unsigned int*)tags);
    expT_kernel<<<(TT * TT + 127) / 128, 128>>>(trans);
    gold_kernel<<<BB, 128>>>(emis, tags, trans);
    forward_kernel<<<BB, TT>>>(emis);
    finalize_kernel<<<1, BB>>>(out);
}